// round 6
// baseline (speedup 1.0000x reference)
#include <cuda_runtime.h>
#include <math.h>
#include <stdint.h>

// ---------------- problem constants ----------------
#define BB   8
#define CC   128
#define H0   62
#define W0   62
#define HH   64
#define WW   64
#define HP   66
#define WP   66
#define GG   4
#define PP   9
#define GC   32
#define NPIX (BB*HH*WW)        // 32768
#define OMS  128               // padded om row stride
#define LDA  132

// ---------------- scratch (device globals) ----------------
__device__ float g_xpad[BB*HH*WW*CC];   // x NHWC (tf32 values), zero ring
__device__ float g_y   [BB*HH*WW*CC];   // conv1x1 output NHWC
__device__ float g_xp  [BB*HP*WP*CC];   // x_proj padded NHWC
__device__ float g_om  [NPIX*OMS];      // offsets(72)+logits(36)+pad
__device__ float g_bt  [4*128*128];     // 4 pre-transposed tf32 B tiles [k][n]
__device__ float g_bcat[128];           // padded off/mask bias

// ---------------- helpers ----------------
__device__ __forceinline__ float f2tf(float x) {
    uint32_t u;
    asm("cvt.rn.tf32.f32 %0, %1;" : "=r"(u) : "f"(x));
    return __uint_as_float(u);
}
__device__ __forceinline__ void mma_tf32(float c[4], const uint32_t a[4],
                                         uint32_t b0, uint32_t b1) {
    asm volatile(
        "mma.sync.aligned.m16n8k8.row.col.f32.tf32.tf32.f32 "
        "{%0,%1,%2,%3}, {%4,%5,%6,%7}, {%8,%9}, {%0,%1,%2,%3};"
        : "+f"(c[0]), "+f"(c[1]), "+f"(c[2]), "+f"(c[3])
        : "r"(a[0]), "r"(a[1]), "r"(a[2]), "r"(a[3]), "r"(b0), "r"(b1));
}

// ---------------- prep: weights + pad-ring zero (merged) ----------------
#define TBW   (4*128*128)
#define RINGN (BB*260*32)
__global__ void prep_kernel(const float* __restrict__ conv_w,
                            const float* __restrict__ in_proj_w,
                            const float* __restrict__ off_w,
                            const float* __restrict__ mask_w,
                            const float* __restrict__ off_b,
                            const float* __restrict__ mask_b,
                            const float* __restrict__ out_proj_w) {
    int idx = blockIdx.x * blockDim.x + threadIdx.x;
    if (idx < TBW) {
        int w = idx >> 14;
        int rem = idx & 16383;
        int k = rem >> 7, n = rem & 127;
        float v;
        if (w == 0)      v = conv_w[n * 128 + k];
        else if (w == 1) v = in_proj_w[k * 128 + n];
        else if (w == 2) v = (n < 72) ? off_w[k * 72 + n]
                           : (n < 108) ? mask_w[k * 36 + (n - 72)] : 0.f;
        else             v = out_proj_w[k * 128 + n];
        g_bt[idx] = f2tf(v);
    } else if (idx < TBW + 128) {
        int n = idx - TBW;
        g_bcat[n] = (n < 72) ? off_b[n] : (n < 108) ? mask_b[n - 72] : 0.f;
    } else if (idx < TBW + 128 + RINGN) {
        int t = idx - (TBW + 128);
        int c4 = (t & 31) * 4;
        int q = t >> 5;
        int b = q / 260, p = q % 260;
        int r, cl;
        if (p < 66)       { r = 0;        cl = p; }
        else if (p < 132) { r = 65;       cl = p - 66; }
        else if (p < 196) { r = p - 131;  cl = 0; }
        else              { r = p - 195;  cl = 65; }
        *reinterpret_cast<float4*>(&g_xp[(((size_t)b * HP + r) * WP + cl) * CC + c4]) =
            make_float4(0.f, 0.f, 0.f, 0.f);
    }
}

// ---------------- NCHW -> NHWC transpose + pad, pre-converted to tf32 ----------------
__global__ void transpose_pad_kernel(const float* __restrict__ x) {
    __shared__ float s[32][33];
    int bi = blockIdx.x;
    int b = bi >> 6, i = bi & 63;
    int j0 = blockIdx.y * 32, c0 = blockIdx.z * 32;
    int tx = threadIdx.x, ty = threadIdx.y;
    int j = j0 + tx;
    float v = 0.f;
    if (i >= 1 && i <= 62 && j >= 1 && j <= 62)
        v = x[((b * CC + c0 + ty) * H0 + (i - 1)) * W0 + (j - 1)];
    s[ty][tx] = f2tf(v);
    __syncthreads();
    int jw = j0 + ty;
    g_xpad[((b * HH + i) * WW + jw) * CC + c0 + tx] = s[tx][ty];
}

// ================= GEMM machinery =================
// load 128x128 B tile (pre-tf32 [k][n]) : 4096 float4 / 512 thr
__device__ __forceinline__ void load_B(const float* __restrict__ Bt, float* sB, int tid) {
#pragma unroll
    for (int it = 0; it < 8; it++) {
        int idx = it * 512 + tid;
        int r = idx >> 5, c4 = (idx & 31) * 4;
        *reinterpret_cast<float4*>(&sB[r * LDA + c4]) =
            *reinterpret_cast<const float4*>(&Bt[(size_t)r * 128 + c4]);
    }
}

// M=256 stage: 16 warps (4m x 4n), warp 64x32
__device__ __forceinline__ void mma_stage256(const float* sA, const float* sB,
                                             float acc[4][4][4],
                                             int wm, int wn, int g, int tig) {
#pragma unroll
    for (int mt = 0; mt < 4; mt++)
#pragma unroll
        for (int nt = 0; nt < 4; nt++)
#pragma unroll
            for (int q = 0; q < 4; q++) acc[mt][nt][q] = 0.f;
#pragma unroll
    for (int ks = 0; ks < 16; ks++) {
        int k0 = ks * 8;
        uint32_t af[4][4];
#pragma unroll
        for (int mt = 0; mt < 4; mt++) {
            int rb = wm * 64 + mt * 16 + g;
            af[mt][0] = __float_as_uint(sA[rb * LDA + k0 + tig]);
            af[mt][1] = __float_as_uint(sA[(rb + 8) * LDA + k0 + tig]);
            af[mt][2] = __float_as_uint(sA[rb * LDA + k0 + tig + 4]);
            af[mt][3] = __float_as_uint(sA[(rb + 8) * LDA + k0 + tig + 4]);
        }
#pragma unroll
        for (int nt = 0; nt < 4; nt++) {
            int cb = wn * 32 + nt * 8 + g;
            uint32_t b0 = __float_as_uint(sB[(k0 + tig) * LDA + cb]);
            uint32_t b1 = __float_as_uint(sB[(k0 + tig + 4) * LDA + cb]);
#pragma unroll
            for (int mt = 0; mt < 4; mt++) mma_tf32(acc[mt][nt], af[mt], b0, b1);
        }
    }
}

// M=128 stage: 16 warps (4m x 4n), warp 32x32
__device__ __forceinline__ void mma_stage128(const float* sA, const float* sB,
                                             float acc[2][4][4],
                                             int wm, int wn, int g, int tig) {
#pragma unroll
    for (int mt = 0; mt < 2; mt++)
#pragma unroll
        for (int nt = 0; nt < 4; nt++)
#pragma unroll
            for (int q = 0; q < 4; q++) acc[mt][nt][q] = 0.f;
#pragma unroll
    for (int ks = 0; ks < 16; ks++) {
        int k0 = ks * 8;
        uint32_t af[2][4];
#pragma unroll
        for (int mt = 0; mt < 2; mt++) {
            int rb = wm * 32 + mt * 16 + g;
            af[mt][0] = __float_as_uint(sA[rb * LDA + k0 + tig]);
            af[mt][1] = __float_as_uint(sA[(rb + 8) * LDA + k0 + tig]);
            af[mt][2] = __float_as_uint(sA[rb * LDA + k0 + tig + 4]);
            af[mt][3] = __float_as_uint(sA[(rb + 8) * LDA + k0 + tig + 4]);
        }
#pragma unroll
        for (int nt = 0; nt < 4; nt++) {
            int cb = wn * 32 + nt * 8 + g;
            uint32_t b0 = __float_as_uint(sB[(k0 + tig) * LDA + cb]);
            uint32_t b1 = __float_as_uint(sB[(k0 + tig + 4) * LDA + cb]);
            mma_tf32(acc[0][nt], af[0], b0, b1);
            mma_tf32(acc[1][nt], af[1], b0, b1);
        }
    }
}

#define SMEM_DUAL ((256*LDA + 128*LDA) * 4)   // 202752
#define SMEM_128  ((128*LDA + 128*LDA) * 4)   // 135168

// ---------------- fused GEMM1+GEMM2 ----------------
__global__ __launch_bounds__(512) void dual_gemm_kernel(
    const float* __restrict__ Bt1, const float* __restrict__ bias1,
    const float* __restrict__ Bt2, const float* __restrict__ bias2) {
    extern __shared__ float sm[];
    float* sA = sm;                 // 256 x 132
    float* sB = sm + 256 * LDA;     // 128 x 132
    int tid = threadIdx.x;
    int w = tid >> 5, lane = tid & 31;
    int g = lane >> 2, tig = lane & 3;
    int wm = w >> 2, wn = w & 3;
    int m0 = blockIdx.x * 256;

    // A tile (already tf32-valued) : 8192 float4
#pragma unroll
    for (int it = 0; it < 16; it++) {
        int idx = it * 512 + tid;
        int r = idx >> 5, c4 = (idx & 31) * 4;
        *reinterpret_cast<float4*>(&sA[r * LDA + c4]) =
            *reinterpret_cast<const float4*>(&g_xpad[(size_t)(m0 + r) * 128 + c4]);
    }
    load_B(Bt1, sB, tid);
    __syncthreads();

    float acc[4][4][4];
    mma_stage256(sA, sB, acc, wm, wn, g, tig);
    __syncthreads();

    // epilogue 1: tf32(y) into sA for stage 2
#pragma unroll
    for (int mt = 0; mt < 4; mt++) {
        int ml = wm * 64 + mt * 16 + g;
#pragma unroll
        for (int nt = 0; nt < 4; nt++) {
            int cb = wn * 32 + nt * 8 + 2 * tig;
            float bx = __ldg(&bias1[cb]), by = __ldg(&bias1[cb + 1]);
            sA[ml * LDA + cb]           = f2tf(acc[mt][nt][0] + bx);
            sA[ml * LDA + cb + 1]       = f2tf(acc[mt][nt][1] + by);
            sA[(ml + 8) * LDA + cb]     = f2tf(acc[mt][nt][2] + bx);
            sA[(ml + 8) * LDA + cb + 1] = f2tf(acc[mt][nt][3] + by);
        }
    }
    // staged coalesced g_y write, two 128-row halves through sB
#pragma unroll
    for (int h = 0; h < 2; h++) {
        if ((wm >> 1) == h) {
            int wml = (wm & 1);
#pragma unroll
            for (int mt = 0; mt < 4; mt++) {
                int ml = wml * 64 + mt * 16 + g;
#pragma unroll
                for (int nt = 0; nt < 4; nt++) {
                    int cb = wn * 32 + nt * 8 + 2 * tig;
                    float bx = __ldg(&bias1[cb]), by = __ldg(&bias1[cb + 1]);
                    sB[ml * LDA + cb]           = acc[mt][nt][0] + bx;
                    sB[ml * LDA + cb + 1]       = acc[mt][nt][1] + by;
                    sB[(ml + 8) * LDA + cb]     = acc[mt][nt][2] + bx;
                    sB[(ml + 8) * LDA + cb + 1] = acc[mt][nt][3] + by;
                }
            }
        }
        __syncthreads();
#pragma unroll
        for (int it = 0; it < 8; it++) {
            int idx = it * 512 + tid;
            int r = idx >> 5, c4 = (idx & 31) * 4;
            *reinterpret_cast<float4*>(&g_y[(size_t)(m0 + h * 128 + r) * 128 + c4]) =
                *reinterpret_cast<const float4*>(&sB[r * LDA + c4]);
        }
        __syncthreads();
    }

    load_B(Bt2, sB, tid);
    __syncthreads();
    mma_stage256(sA, sB, acc, wm, wn, g, tig);
    __syncthreads();

    // epilogue 2: fp32 xp into sA, then coalesced copy to padded g_xp
#pragma unroll
    for (int mt = 0; mt < 4; mt++) {
        int ml = wm * 64 + mt * 16 + g;
#pragma unroll
        for (int nt = 0; nt < 4; nt++) {
            int cb = wn * 32 + nt * 8 + 2 * tig;
            float bx = __ldg(&bias2[cb]), by = __ldg(&bias2[cb + 1]);
            sA[ml * LDA + cb]           = acc[mt][nt][0] + bx;
            sA[ml * LDA + cb + 1]       = acc[mt][nt][1] + by;
            sA[(ml + 8) * LDA + cb]     = acc[mt][nt][2] + bx;
            sA[(ml + 8) * LDA + cb + 1] = acc[mt][nt][3] + by;
        }
    }
    __syncthreads();
    {
        int b = m0 >> 12, rem0 = m0 & 4095;
        int r0 = rem0 >> 6;
#pragma unroll
        for (int it = 0; it < 16; it++) {
            int idx = it * 512 + tid;
            int pl = idx >> 5, c4 = (idx & 31) * 4;
            int rr = pl >> 6, cl = pl & 63;
            *reinterpret_cast<float4*>(
                &g_xp[(((size_t)b * HP + r0 + rr + 1) * WP + cl + 1) * CC + c4]) =
                *reinterpret_cast<const float4*>(&sA[pl * LDA + c4]);
        }
    }
}

// ---------------- fused dw3x3 + LN + GELU + offset/mask GEMM ----------------
__global__ __launch_bounds__(512) void dwproj_kernel(
    const float* __restrict__ dw_w, const float* __restrict__ dw_b,
    const float* __restrict__ ln_g, const float* __restrict__ ln_b,
    const float* __restrict__ Bt, const float* __restrict__ bias) {
    extern __shared__ float sm[];
    float* sA = sm;                 // 128 x 132
    float* sB = sm + 128 * LDA;     // 128 x 132
    __shared__ float dws[CC * 9];
    int tid = threadIdx.x;
    int w = tid >> 5, lane = tid & 31;
    int g = lane >> 2, tig = lane & 3;
    int wm = w >> 2, wn = w & 3;
    int m0 = blockIdx.x * 128;
    int b = m0 >> 12;

    for (int t = tid; t < CC * 9; t += 512) dws[t] = dw_w[t];
    load_B(Bt, sB, tid);
    __syncthreads();

    // phase 1: d for 128 pixels, tf32 into sA
    int c4 = lane * 4;
    float4 db = *reinterpret_cast<const float4*>(&dw_b[c4]);
    float4 lgv = *reinterpret_cast<const float4*>(&ln_g[c4]);
    float4 lbv = *reinterpret_cast<const float4*>(&ln_b[c4]);
#pragma unroll
    for (int pass = 0; pass < 8; pass++) {
        int pl = pass * 16 + w;
        int rem = (m0 + pl) & 4095;
        int i = rem >> 6, j = rem & 63;
        float v[4] = {db.x, db.y, db.z, db.w};
#pragma unroll
        for (int ky = 0; ky < 3; ky++)
#pragma unroll
            for (int kx = 0; kx < 3; kx++) {
                int yy = i + ky - 1, xx = j + kx - 1;
                if ((unsigned)yy < (unsigned)HH && (unsigned)xx < (unsigned)WW) {
                    float4 yv = *reinterpret_cast<const float4*>(
                        &g_y[((size_t)(b * HH + yy) * WW + xx) * CC + c4]);
                    int t = ky * 3 + kx;
                    v[0] += yv.x * dws[(c4 + 0) * 9 + t];
                    v[1] += yv.y * dws[(c4 + 1) * 9 + t];
                    v[2] += yv.z * dws[(c4 + 2) * 9 + t];
                    v[3] += yv.w * dws[(c4 + 3) * 9 + t];
                }
            }
        float s = v[0] + v[1] + v[2] + v[3];
#pragma unroll
        for (int o = 16; o; o >>= 1) s += __shfl_xor_sync(0xffffffffu, s, o);
        float mu = s * (1.f / 128.f);
        float d2 = 0.f;
#pragma unroll
        for (int q = 0; q < 4; q++) { float t = v[q] - mu; d2 += t * t; }
#pragma unroll
        for (int o = 16; o; o >>= 1) d2 += __shfl_xor_sync(0xffffffffu, d2, o);
        float inv = rsqrtf(d2 * (1.f / 128.f) + 1e-5f);
        float gq[4] = {lgv.x, lgv.y, lgv.z, lgv.w};
        float bq[4] = {lbv.x, lbv.y, lbv.z, lbv.w};
        float4 outv;
        float* op = reinterpret_cast<float*>(&outv);
#pragma unroll
        for (int q = 0; q < 4; q++) {
            float t = (v[q] - mu) * inv * gq[q] + bq[q];
            op[q] = f2tf(0.5f * t * (1.f + erff(t * 0.70710678118654752440f)));
        }
        *reinterpret_cast<float4*>(&sA[pl * LDA + c4]) = outv;
    }
    __syncthreads();

    float acc[2][4][4];
    mma_stage128(sA, sB, acc, wm, wn, g, tig);
    __syncthreads();

    // stage fp32 result in sB, coalesced write to g_om
#pragma unroll
    for (int mt = 0; mt < 2; mt++) {
        int ml = wm * 32 + mt * 16 + g;
#pragma unroll
        for (int nt = 0; nt < 4; nt++) {
            int cb = wn * 32 + nt * 8 + 2 * tig;
            float bx = __ldg(&bias[cb]), by = __ldg(&bias[cb + 1]);
            sB[ml * LDA + cb]           = acc[mt][nt][0] + bx;
            sB[ml * LDA + cb + 1]       = acc[mt][nt][1] + by;
            sB[(ml + 8) * LDA + cb]     = acc[mt][nt][2] + bx;
            sB[(ml + 8) * LDA + cb + 1] = acc[mt][nt][3] + by;
        }
    }
    __syncthreads();
#pragma unroll
    for (int it = 0; it < 8; it++) {
        int idx = it * 512 + tid;
        int r = idx >> 5, cc4 = (idx & 31) * 4;
        *reinterpret_cast<float4*>(&g_om[(size_t)(m0 + r) * OMS + cc4]) =
            *reinterpret_cast<const float4*>(&sB[r * LDA + cc4]);
    }
}

// ---------------- fused softmax + bilinear sampling + out_proj GEMM ----------------
__global__ __launch_bounds__(512) void sampproj_kernel(
    const float* __restrict__ Bt, const float* __restrict__ bias,
    float* __restrict__ out) {
    extern __shared__ float sm[];
    float* sA = sm;                 // 128 x 132 (sampled tf32, later [c][pix] staging)
    float* sB = sm + 128 * LDA;     // 128 x 132 (out_proj B)
    int tid = threadIdx.x;
    int w = tid >> 5, lane = tid & 31;
    int g = lane >> 2, tig = lane & 3;
    int wm = w >> 2, wn = w & 3;
    int m0 = blockIdx.x * 128;
    int b = m0 >> 12, rem0 = m0 & 4095;

    load_B(Bt, sB, tid);

    const float* xpb = g_xp + (size_t)b * (HP * WP * CC);
#pragma unroll 1
    for (int t = 0; t < 32; t++) {
        int task = w * 32 + t;
        int pl = task >> 2, gq = task & 3;
        int rem = (m0 + pl) & 4095;
        int i = rem >> 6, j = rem & 63;
        const float* omr = g_om + (size_t)(m0 + pl) * OMS;

        float lg[9];
        float mx = -1e30f;
#pragma unroll
        for (int p = 0; p < 9; p++) { lg[p] = omr[72 + gq * 9 + p]; mx = fmaxf(mx, lg[p]); }
        float sum = 0.f;
#pragma unroll
        for (int p = 0; p < 9; p++) { lg[p] = expf(lg[p] - mx); sum += lg[p]; }
        float minv = 1.f / sum;

        int cbase = gq * GC + lane;
        float acc = 0.f;
#pragma unroll
        for (int p = 0; p < 9; p++) {
            float offx = omr[(gq * 9 + p) * 2 + 0];
            float offy = omr[(gq * 9 + p) * 2 + 1];
            float ix = (float)(j + p / 3) + offx;
            float iy = (float)(i + (p - (p / 3) * 3)) + offy;
            float x0f = floorf(ix), y0f = floorf(iy);
            float wx1 = ix - x0f, wy1 = iy - y0f;
            float wx0 = 1.f - wx1, wy0 = 1.f - wy1;
            int x0 = (int)x0f, y0 = (int)y0f;
            float v00 = 0.f, v10 = 0.f, v01 = 0.f, v11 = 0.f;
            bool xv0 = (x0 >= 0) & (x0 < WP);
            bool xv1 = (x0 + 1 >= 0) & (x0 + 1 < WP);
            bool yv0 = (y0 >= 0) & (y0 < HP);
            bool yv1 = (y0 + 1 >= 0) & (y0 + 1 < HP);
            if (yv0) {
                if (xv0) v00 = xpb[(y0 * WP + x0) * CC + cbase];
                if (xv1) v10 = xpb[(y0 * WP + x0 + 1) * CC + cbase];
            }
            if (yv1) {
                if (xv0) v01 = xpb[((y0 + 1) * WP + x0) * CC + cbase];
                if (xv1) v11 = xpb[((y0 + 1) * WP + x0 + 1) * CC + cbase];
            }
            float bi = (v00 * wx0 + v10 * wx1) * wy0 + (v01 * wx0 + v11 * wx1) * wy1;
            acc += (lg[p] * minv) * bi;
        }
        sA[pl * LDA + cbase] = f2tf(acc);
    }
    __syncthreads();

    float acc[2][4][4];
    mma_stage128(sA, sB, acc, wm, wn, g, tig);
    __syncthreads();

    // stage transposed [c][pix] in sA, coalesced NCHW write
#pragma unroll
    for (int mt = 0; mt < 2; mt++) {
        int ml = wm * 32 + mt * 16 + g;
#pragma unroll
        for (int nt = 0; nt < 4; nt++) {
            int cb = wn * 32 + nt * 8 + 2 * tig;
            float bx = __ldg(&bias[cb]), by = __ldg(&bias[cb + 1]);
            sA[cb * LDA + ml]           = acc[mt][nt][0] + bx;
            sA[(cb + 1) * LDA + ml]     = acc[mt][nt][1] + by;
            sA[cb * LDA + ml + 8]       = acc[mt][nt][2] + bx;
            sA[(cb + 1) * LDA + ml + 8] = acc[mt][nt][3] + by;
        }
    }
    __syncthreads();
#pragma unroll
    for (int it = 0; it < 8; it++) {
        int idx = it * 512 + tid;
        int c = idx >> 5, p4 = (idx & 31) * 4;
        *reinterpret_cast<float4*>(&out[((size_t)b * CC + c) * 4096 + rem0 + p4]) =
            *reinterpret_cast<const float4*>(&sA[c * LDA + p4]);
    }
}

// ---------------- launch ----------------
extern "C" void kernel_launch(void* const* d_in, const int* in_sizes, int n_in,
                              void* d_out, int out_size) {
    const float* x          = (const float*)d_in[0];
    const float* conv_w     = (const float*)d_in[1];
    const float* conv_b     = (const float*)d_in[2];
    const float* in_proj_w  = (const float*)d_in[3];
    const float* in_proj_b  = (const float*)d_in[4];
    const float* dw_w       = (const float*)d_in[5];
    const float* dw_b       = (const float*)d_in[6];
    const float* ln_g       = (const float*)d_in[7];
    const float* ln_b       = (const float*)d_in[8];
    const float* off_w      = (const float*)d_in[9];
    const float* off_b      = (const float*)d_in[10];
    const float* mask_w     = (const float*)d_in[11];
    const float* mask_b     = (const float*)d_in[12];
    const float* out_proj_w = (const float*)d_in[13];
    const float* out_proj_b = (const float*)d_in[14];
    float* out = (float*)d_out;

    float *p_bt, *p_bcat;
    cudaGetSymbolAddress((void**)&p_bt,   g_bt);
    cudaGetSymbolAddress((void**)&p_bcat, g_bcat);

    cudaFuncSetAttribute(dual_gemm_kernel,
                         cudaFuncAttributeMaxDynamicSharedMemorySize, SMEM_DUAL);
    cudaFuncSetAttribute(dwproj_kernel,
                         cudaFuncAttributeMaxDynamicSharedMemorySize, SMEM_128);
    cudaFuncSetAttribute(sampproj_kernel,
                         cudaFuncAttributeMaxDynamicSharedMemorySize, SMEM_128);

    // 1. weights + ring zero
    prep_kernel<<<(TBW + 128 + RINGN + 255) / 256, 256>>>(
        conv_w, in_proj_w, off_w, mask_w, off_b, mask_b, out_proj_w);
    // 2. NCHW -> NHWC transpose + pad (tf32 values)
    {
        dim3 grid(BB * HH, WW / 32, CC / 32);
        transpose_pad_kernel<<<grid, dim3(32, 32)>>>(x);
    }
    // 3. fused GEMM1+GEMM2 -> g_y, g_xp
    dual_gemm_kernel<<<NPIX / 256, 512, SMEM_DUAL>>>(
        p_bt + 0 * 16384, conv_b, p_bt + 1 * 16384, in_proj_b);
    // 4. fused dw+LN+GELU+GEMM3 -> g_om
    dwproj_kernel<<<NPIX / 128, 512, SMEM_128>>>(
        dw_w, dw_b, ln_g, ln_b, p_bt + 2 * 16384, p_bcat);
    // 5. fused sampling+GEMM4 -> out (NCHW)
    sampproj_kernel<<<NPIX / 128, 512, SMEM_128>>>(
        p_bt + 3 * 16384, out_proj_b, out);
}

// round 7
// speedup vs baseline: 1.1522x; 1.1522x over previous
#include <cuda_runtime.h>
#include <math.h>
#include <stdint.h>

// ---------------- problem constants ----------------
#define BB   8
#define CC   128
#define H0   62
#define W0   62
#define HH   64
#define WW   64
#define HP   66
#define WP   66
#define GG   4
#define PP   9
#define GC   32
#define NPIX (BB*HH*WW)        // 32768
#define OMS  128               // padded om row stride
#define LDA  132

// ---------------- scratch (device globals) ----------------
__device__ float g_xpad[BB*HH*WW*CC];   // x NHWC (tf32 values), zero ring
__device__ float g_y   [BB*HH*WW*CC];   // conv1x1 output NHWC
__device__ float g_xp  [BB*HP*WP*CC];   // x_proj padded NHWC
__device__ float g_d   [BB*HH*WW*CC];   // dw+LN+GELU NHWC (tf32 values)
__device__ float g_om  [NPIX*OMS];      // offsets(72)+logits(36)+pad
__device__ float g_sam [NPIX*CC];       // sampled NHWC
__device__ float g_bt  [4*128*128];     // 4 pre-transposed tf32 B tiles [k][n]
__device__ float g_bcat[128];           // padded off/mask bias

// ---------------- helpers ----------------
__device__ __forceinline__ float f2tf(float x) {
    uint32_t u;
    asm("cvt.rn.tf32.f32 %0, %1;" : "=r"(u) : "f"(x));
    return __uint_as_float(u);
}
__device__ __forceinline__ void mma_tf32(float c[4], const uint32_t a[4],
                                         uint32_t b0, uint32_t b1) {
    asm volatile(
        "mma.sync.aligned.m16n8k8.row.col.f32.tf32.tf32.f32 "
        "{%0,%1,%2,%3}, {%4,%5,%6,%7}, {%8,%9}, {%0,%1,%2,%3};"
        : "+f"(c[0]), "+f"(c[1]), "+f"(c[2]), "+f"(c[3])
        : "r"(a[0]), "r"(a[1]), "r"(a[2]), "r"(a[3]), "r"(b0), "r"(b1));
}

// ---------------- prep: weights + pad-ring zero (merged) ----------------
#define TBW   (4*128*128)
#define RINGN (BB*260*32)
__global__ void prep_kernel(const float* __restrict__ conv_w,
                            const float* __restrict__ in_proj_w,
                            const float* __restrict__ off_w,
                            const float* __restrict__ mask_w,
                            const float* __restrict__ off_b,
                            const float* __restrict__ mask_b,
                            const float* __restrict__ out_proj_w) {
    int idx = blockIdx.x * blockDim.x + threadIdx.x;
    if (idx < TBW) {
        int w = idx >> 14;
        int rem = idx & 16383;
        int k = rem >> 7, n = rem & 127;
        float v;
        if (w == 0)      v = conv_w[n * 128 + k];
        else if (w == 1) v = in_proj_w[k * 128 + n];
        else if (w == 2) v = (n < 72) ? off_w[k * 72 + n]
                           : (n < 108) ? mask_w[k * 36 + (n - 72)] : 0.f;
        else             v = out_proj_w[k * 128 + n];
        g_bt[idx] = f2tf(v);
    } else if (idx < TBW + 128) {
        int n = idx - TBW;
        g_bcat[n] = (n < 72) ? off_b[n] : (n < 108) ? mask_b[n - 72] : 0.f;
    } else if (idx < TBW + 128 + RINGN) {
        int t = idx - (TBW + 128);
        int c4 = (t & 31) * 4;
        int q = t >> 5;
        int b = q / 260, p = q % 260;
        int r, cl;
        if (p < 66)       { r = 0;        cl = p; }
        else if (p < 132) { r = 65;       cl = p - 66; }
        else if (p < 196) { r = p - 131;  cl = 0; }
        else              { r = p - 195;  cl = 65; }
        *reinterpret_cast<float4*>(&g_xp[(((size_t)b * HP + r) * WP + cl) * CC + c4]) =
            make_float4(0.f, 0.f, 0.f, 0.f);
    }
}

// ---------------- NCHW -> NHWC transpose + pad, pre-converted to tf32 ----------------
__global__ void transpose_pad_kernel(const float* __restrict__ x) {
    __shared__ float s[32][33];
    int bi = blockIdx.x;
    int b = bi >> 6, i = bi & 63;
    int j0 = blockIdx.y * 32, c0 = blockIdx.z * 32;
    int tx = threadIdx.x, ty = threadIdx.y;
    int j = j0 + tx;
    float v = 0.f;
    if (i >= 1 && i <= 62 && j >= 1 && j <= 62)
        v = x[((b * CC + c0 + ty) * H0 + (i - 1)) * W0 + (j - 1)];
    s[ty][tx] = f2tf(v);
    __syncthreads();
    int jw = j0 + ty;
    g_xpad[((b * HH + i) * WW + jw) * CC + c0 + tx] = s[tx][ty];
}

// ================= GEMM machinery =================
__device__ __forceinline__ void load_B(const float* __restrict__ Bt, float* sB, int tid) {
#pragma unroll
    for (int it = 0; it < 8; it++) {
        int idx = it * 512 + tid;
        int r = idx >> 5, c4 = (idx & 31) * 4;
        *reinterpret_cast<float4*>(&sB[r * LDA + c4]) =
            *reinterpret_cast<const float4*>(&Bt[(size_t)r * 128 + c4]);
    }
}
// M=256 stage: 16 warps (4m x 4n), warp 64x32
__device__ __forceinline__ void mma_stage256(const float* sA, const float* sB,
                                             float acc[4][4][4],
                                             int wm, int wn, int g, int tig) {
#pragma unroll
    for (int mt = 0; mt < 4; mt++)
#pragma unroll
        for (int nt = 0; nt < 4; nt++)
#pragma unroll
            for (int q = 0; q < 4; q++) acc[mt][nt][q] = 0.f;
#pragma unroll
    for (int ks = 0; ks < 16; ks++) {
        int k0 = ks * 8;
        uint32_t af[4][4];
#pragma unroll
        for (int mt = 0; mt < 4; mt++) {
            int rb = wm * 64 + mt * 16 + g;
            af[mt][0] = __float_as_uint(sA[rb * LDA + k0 + tig]);
            af[mt][1] = __float_as_uint(sA[(rb + 8) * LDA + k0 + tig]);
            af[mt][2] = __float_as_uint(sA[rb * LDA + k0 + tig + 4]);
            af[mt][3] = __float_as_uint(sA[(rb + 8) * LDA + k0 + tig + 4]);
        }
#pragma unroll
        for (int nt = 0; nt < 4; nt++) {
            int cb = wn * 32 + nt * 8 + g;
            uint32_t b0 = __float_as_uint(sB[(k0 + tig) * LDA + cb]);
            uint32_t b1 = __float_as_uint(sB[(k0 + tig + 4) * LDA + cb]);
#pragma unroll
            for (int mt = 0; mt < 4; mt++) mma_tf32(acc[mt][nt], af[mt], b0, b1);
        }
    }
}

#define SMEM_DUAL ((256*LDA + 128*LDA) * 4)   // 202752

// ---------------- fused GEMM1+GEMM2 ----------------
__global__ __launch_bounds__(512) void dual_gemm_kernel(
    const float* __restrict__ Bt1, const float* __restrict__ bias1,
    const float* __restrict__ Bt2, const float* __restrict__ bias2) {
    extern __shared__ float sm[];
    float* sA = sm;                 // 256 x 132
    float* sB = sm + 256 * LDA;     // 128 x 132
    int tid = threadIdx.x;
    int w = tid >> 5, lane = tid & 31;
    int g = lane >> 2, tig = lane & 3;
    int wm = w >> 2, wn = w & 3;
    int m0 = blockIdx.x * 256;

#pragma unroll
    for (int it = 0; it < 16; it++) {
        int idx = it * 512 + tid;
        int r = idx >> 5, c4 = (idx & 31) * 4;
        *reinterpret_cast<float4*>(&sA[r * LDA + c4]) =
            *reinterpret_cast<const float4*>(&g_xpad[(size_t)(m0 + r) * 128 + c4]);
    }
    load_B(Bt1, sB, tid);
    __syncthreads();

    float acc[4][4][4];
    mma_stage256(sA, sB, acc, wm, wn, g, tig);
    __syncthreads();

    // epilogue 1: tf32(y) into sA for stage 2
#pragma unroll
    for (int mt = 0; mt < 4; mt++) {
        int ml = wm * 64 + mt * 16 + g;
#pragma unroll
        for (int nt = 0; nt < 4; nt++) {
            int cb = wn * 32 + nt * 8 + 2 * tig;
            float bx = __ldg(&bias1[cb]), by = __ldg(&bias1[cb + 1]);
            sA[ml * LDA + cb]           = f2tf(acc[mt][nt][0] + bx);
            sA[ml * LDA + cb + 1]       = f2tf(acc[mt][nt][1] + by);
            sA[(ml + 8) * LDA + cb]     = f2tf(acc[mt][nt][2] + bx);
            sA[(ml + 8) * LDA + cb + 1] = f2tf(acc[mt][nt][3] + by);
        }
    }
    // staged coalesced g_y write, two 128-row halves through sB
#pragma unroll
    for (int h = 0; h < 2; h++) {
        if ((wm >> 1) == h) {
            int wml = (wm & 1);
#pragma unroll
            for (int mt = 0; mt < 4; mt++) {
                int ml = wml * 64 + mt * 16 + g;
#pragma unroll
                for (int nt = 0; nt < 4; nt++) {
                    int cb = wn * 32 + nt * 8 + 2 * tig;
                    float bx = __ldg(&bias1[cb]), by = __ldg(&bias1[cb + 1]);
                    sB[ml * LDA + cb]           = acc[mt][nt][0] + bx;
                    sB[ml * LDA + cb + 1]       = acc[mt][nt][1] + by;
                    sB[(ml + 8) * LDA + cb]     = acc[mt][nt][2] + bx;
                    sB[(ml + 8) * LDA + cb + 1] = acc[mt][nt][3] + by;
                }
            }
        }
        __syncthreads();
#pragma unroll
        for (int it = 0; it < 8; it++) {
            int idx = it * 512 + tid;
            int r = idx >> 5, c4 = (idx & 31) * 4;
            *reinterpret_cast<float4*>(&g_y[(size_t)(m0 + h * 128 + r) * 128 + c4]) =
                *reinterpret_cast<const float4*>(&sB[r * LDA + c4]);
        }
        __syncthreads();
    }

    load_B(Bt2, sB, tid);
    __syncthreads();
    mma_stage256(sA, sB, acc, wm, wn, g, tig);
    __syncthreads();

    // epilogue 2: fp32 xp into sA, coalesced copy to padded g_xp
#pragma unroll
    for (int mt = 0; mt < 4; mt++) {
        int ml = wm * 64 + mt * 16 + g;
#pragma unroll
        for (int nt = 0; nt < 4; nt++) {
            int cb = wn * 32 + nt * 8 + 2 * tig;
            float bx = __ldg(&bias2[cb]), by = __ldg(&bias2[cb + 1]);
            sA[ml * LDA + cb]           = acc[mt][nt][0] + bx;
            sA[ml * LDA + cb + 1]       = acc[mt][nt][1] + by;
            sA[(ml + 8) * LDA + cb]     = acc[mt][nt][2] + bx;
            sA[(ml + 8) * LDA + cb + 1] = acc[mt][nt][3] + by;
        }
    }
    __syncthreads();
    {
        int b = m0 >> 12, rem0 = m0 & 4095;
        int r0 = rem0 >> 6;
#pragma unroll
        for (int it = 0; it < 16; it++) {
            int idx = it * 512 + tid;
            int pl = idx >> 5, c4 = (idx & 31) * 4;
            int rr = pl >> 6, cl = pl & 63;
            *reinterpret_cast<float4*>(
                &g_xp[(((size_t)b * HP + r0 + rr + 1) * WP + cl + 1) * CC + c4]) =
                *reinterpret_cast<const float4*>(&sA[pl * LDA + c4]);
        }
    }
}

// ---------------- single GEMM M=256 (mode 0: g_om rows; mode 2: NCHW via transpose) ----
__global__ __launch_bounds__(512) void mma_gemm_kernel(
    const float* __restrict__ A, const float* __restrict__ Bt,
    const float* __restrict__ bias, float* __restrict__ C, int mode) {
    extern __shared__ float sm[];
    float* sA = sm;
    float* sB = sm + 256 * LDA;
    int tid = threadIdx.x;
    int w = tid >> 5, lane = tid & 31;
    int g = lane >> 2, tig = lane & 3;
    int wm = w >> 2, wn = w & 3;
    int m0 = blockIdx.x * 256;

#pragma unroll
    for (int it = 0; it < 16; it++) {
        int idx = it * 512 + tid;
        int r = idx >> 5, c4 = (idx & 31) * 4;
        *reinterpret_cast<float4*>(&sA[r * LDA + c4]) =
            *reinterpret_cast<const float4*>(&A[(size_t)(m0 + r) * 128 + c4]);
    }
    load_B(Bt, sB, tid);
    __syncthreads();

    float acc[4][4][4];
    mma_stage256(sA, sB, acc, wm, wn, g, tig);
    __syncthreads();

    if (mode == 0) {
        // stage [pix][c] fp32, write 256 coalesced 512B rows to g_om
#pragma unroll
        for (int mt = 0; mt < 4; mt++) {
            int ml = wm * 64 + mt * 16 + g;
#pragma unroll
            for (int nt = 0; nt < 4; nt++) {
                int cb = wn * 32 + nt * 8 + 2 * tig;
                float bx = __ldg(&bias[cb]), by = __ldg(&bias[cb + 1]);
                sA[ml * LDA + cb]           = acc[mt][nt][0] + bx;
                sA[ml * LDA + cb + 1]       = acc[mt][nt][1] + by;
                sA[(ml + 8) * LDA + cb]     = acc[mt][nt][2] + bx;
                sA[(ml + 8) * LDA + cb + 1] = acc[mt][nt][3] + by;
            }
        }
        __syncthreads();
#pragma unroll
        for (int it = 0; it < 16; it++) {
            int idx = it * 512 + tid;
            int r = idx >> 5, c4 = (idx & 31) * 4;
            *reinterpret_cast<float4*>(&C[(size_t)(m0 + r) * OMS + c4]) =
                *reinterpret_cast<const float4*>(&sA[r * LDA + c4]);
        }
    } else {
        // stage transposed [c][256 pix] (LDT=260, conflict-free), write NCHW rows
        float* sS = sm;   // 128*260 floats = 33280 <= 256*LDA
#pragma unroll
        for (int mt = 0; mt < 4; mt++) {
            int ml = wm * 64 + mt * 16 + g;
#pragma unroll
            for (int nt = 0; nt < 4; nt++) {
                int cb = wn * 32 + nt * 8 + 2 * tig;
                float bx = __ldg(&bias[cb]), by = __ldg(&bias[cb + 1]);
                sS[cb * 260 + ml]           = acc[mt][nt][0] + bx;
                sS[(cb + 1) * 260 + ml]     = acc[mt][nt][1] + by;
                sS[cb * 260 + ml + 8]       = acc[mt][nt][2] + bx;
                sS[(cb + 1) * 260 + ml + 8] = acc[mt][nt][3] + by;
            }
        }
        __syncthreads();
        int b = m0 >> 12, rem0 = m0 & 4095;
#pragma unroll
        for (int it = 0; it < 16; it++) {
            int idx = it * 512 + tid;
            int c = idx >> 6, p4 = (idx & 63) * 4;
            *reinterpret_cast<float4*>(&C[((size_t)b * CC + c) * 4096 + rem0 + p4]) =
                *reinterpret_cast<const float4*>(&sS[c * 260 + p4]);
        }
    }
}

// ---------------- fused depthwise 3x3 + LayerNorm + GELU (tf32 out) ----------------
__global__ __launch_bounds__(256) void dw_ln_gelu_kernel(
    const float* __restrict__ dw_w, const float* __restrict__ dw_b,
    const float* __restrict__ ln_g, const float* __restrict__ ln_b) {
    __shared__ float dws[CC * 9];
    int tid = threadIdx.x;
    for (int t = tid; t < CC * 9; t += 256) dws[t] = dw_w[t];
    __syncthreads();

    int warp = tid >> 5, lane = tid & 31;
    int pix = blockIdx.x * 8 + warp;
    int b = pix >> 12, rem = pix & 4095;
    int i = rem >> 6, j = rem & 63;
    int c4 = lane * 4;

    float4 db = *reinterpret_cast<const float4*>(&dw_b[c4]);
    float v[4] = {db.x, db.y, db.z, db.w};
#pragma unroll
    for (int ky = 0; ky < 3; ky++)
#pragma unroll
        for (int kx = 0; kx < 3; kx++) {
            int yy = i + ky - 1, xx = j + kx - 1;
            if ((unsigned)yy < (unsigned)HH && (unsigned)xx < (unsigned)WW) {
                float4 yv = *reinterpret_cast<const float4*>(
                    &g_y[((size_t)(b * HH + yy) * WW + xx) * CC + c4]);
                int t = ky * 3 + kx;
                v[0] += yv.x * dws[(c4 + 0) * 9 + t];
                v[1] += yv.y * dws[(c4 + 1) * 9 + t];
                v[2] += yv.z * dws[(c4 + 2) * 9 + t];
                v[3] += yv.w * dws[(c4 + 3) * 9 + t];
            }
        }
    float s = v[0] + v[1] + v[2] + v[3];
#pragma unroll
    for (int o = 16; o; o >>= 1) s += __shfl_xor_sync(0xffffffffu, s, o);
    float mu = s * (1.f / 128.f);
    float d2 = 0.f;
#pragma unroll
    for (int q = 0; q < 4; q++) { float t = v[q] - mu; d2 += t * t; }
#pragma unroll
    for (int o = 16; o; o >>= 1) d2 += __shfl_xor_sync(0xffffffffu, d2, o);
    float inv = rsqrtf(d2 * (1.f / 128.f) + 1e-5f);

    float4 lg = *reinterpret_cast<const float4*>(&ln_g[c4]);
    float4 lb = *reinterpret_cast<const float4*>(&ln_b[c4]);
    float gv[4] = {lg.x, lg.y, lg.z, lg.w};
    float bv[4] = {lb.x, lb.y, lb.z, lb.w};
    float4 outv;
    float* op = reinterpret_cast<float*>(&outv);
#pragma unroll
    for (int q = 0; q < 4; q++) {
        float t = (v[q] - mu) * inv * gv[q] + bv[q];
        op[q] = f2tf(0.5f * t * (1.f + erff(t * 0.70710678118654752440f)));
    }
    *reinterpret_cast<float4*>(&g_d[(size_t)pix * CC + c4]) = outv;
}

// ---------------- DCNv3 core: softmax + bilinear sampling, 8x8 pixel tiles ----------------
// grid = 8 batches * 64 tiles; block 512 = 16 warps; warp does 16 (pixel,group) tasks.
// A CTA's taps land in a ~10x10x512B = 51KB neighborhood -> L1-resident reuse.
__global__ __launch_bounds__(512) void sample_kernel() {
    int w = threadIdx.x >> 5, lane = threadIdx.x & 31;
    int blk = blockIdx.x;
    int b = blk >> 6;
    int i0 = ((blk >> 3) & 7) * 8, j0 = (blk & 7) * 8;
    const float* xpb = g_xp + (size_t)b * (HP * WP * CC);

#pragma unroll 1
    for (int t = 0; t < 16; t++) {
        int task = t * 16 + w;
        int pl = task >> 2, gq = task & 3;
        int i = i0 + (pl >> 3), j = j0 + (pl & 7);
        int pix = (b << 12) + (i << 6) + j;
        const float* omr = g_om + (size_t)pix * OMS;

        float lg[9];
        float mx = -1e30f;
#pragma unroll
        for (int p = 0; p < 9; p++) { lg[p] = omr[72 + gq * 9 + p]; mx = fmaxf(mx, lg[p]); }
        float sum = 0.f;
#pragma unroll
        for (int p = 0; p < 9; p++) { lg[p] = expf(lg[p] - mx); sum += lg[p]; }
        float minv = 1.f / sum;

        int cbase = gq * GC + lane;
        float acc = 0.f;
#pragma unroll
        for (int p = 0; p < 9; p++) {
            float offx = omr[(gq * 9 + p) * 2 + 0];
            float offy = omr[(gq * 9 + p) * 2 + 1];
            float ix = (float)(j + p / 3) + offx;
            float iy = (float)(i + (p - (p / 3) * 3)) + offy;
            float x0f = floorf(ix), y0f = floorf(iy);
            float wx1 = ix - x0f, wy1 = iy - y0f;
            float wx0 = 1.f - wx1, wy0 = 1.f - wy1;
            int x0 = (int)x0f, y0 = (int)y0f;
            float v00 = 0.f, v10 = 0.f, v01 = 0.f, v11 = 0.f;
            bool xv0 = (x0 >= 0) & (x0 < WP);
            bool xv1 = (x0 + 1 >= 0) & (x0 + 1 < WP);
            bool yv0 = (y0 >= 0) & (y0 < HP);
            bool yv1 = (y0 + 1 >= 0) & (y0 + 1 < HP);
            if (yv0) {
                if (xv0) v00 = xpb[(y0 * WP + x0) * CC + cbase];
                if (xv1) v10 = xpb[(y0 * WP + x0 + 1) * CC + cbase];
            }
            if (yv1) {
                if (xv0) v01 = xpb[((y0 + 1) * WP + x0) * CC + cbase];
                if (xv1) v11 = xpb[((y0 + 1) * WP + x0 + 1) * CC + cbase];
            }
            float bi = (v00 * wx0 + v10 * wx1) * wy0 + (v01 * wx0 + v11 * wx1) * wy1;
            acc += (lg[p] * minv) * bi;
        }
        g_sam[(size_t)pix * CC + cbase] = f2tf(acc);
    }
}

// ---------------- launch ----------------
extern "C" void kernel_launch(void* const* d_in, const int* in_sizes, int n_in,
                              void* d_out, int out_size) {
    const float* x          = (const float*)d_in[0];
    const float* conv_w     = (const float*)d_in[1];
    const float* conv_b     = (const float*)d_in[2];
    const float* in_proj_w  = (const float*)d_in[3];
    const float* in_proj_b  = (const float*)d_in[4];
    const float* dw_w       = (const float*)d_in[5];
    const float* dw_b       = (const float*)d_in[6];
    const float* ln_g       = (const float*)d_in[7];
    const float* ln_b       = (const float*)d_in[8];
    const float* off_w      = (const float*)d_in[9];
    const float* off_b      = (const float*)d_in[10];
    const float* mask_w     = (const float*)d_in[11];
    const float* mask_b     = (const float*)d_in[12];
    const float* out_proj_w = (const float*)d_in[13];
    const float* out_proj_b = (const float*)d_in[14];
    float* out = (float*)d_out;

    float *p_d, *p_om, *p_sam, *p_bt, *p_bcat;
    cudaGetSymbolAddress((void**)&p_d,    g_d);
    cudaGetSymbolAddress((void**)&p_om,   g_om);
    cudaGetSymbolAddress((void**)&p_sam,  g_sam);
    cudaGetSymbolAddress((void**)&p_bt,   g_bt);
    cudaGetSymbolAddress((void**)&p_bcat, g_bcat);

    cudaFuncSetAttribute(dual_gemm_kernel,
                         cudaFuncAttributeMaxDynamicSharedMemorySize, SMEM_DUAL);
    cudaFuncSetAttribute(mma_gemm_kernel,
                         cudaFuncAttributeMaxDynamicSharedMemorySize, SMEM_DUAL);

    // 1. weights + ring zero
    prep_kernel<<<(TBW + 128 + RINGN + 255) / 256, 256>>>(
        conv_w, in_proj_w, off_w, mask_w, off_b, mask_b, out_proj_w);
    // 2. NCHW -> NHWC transpose + pad (tf32 values)
    {
        dim3 grid(BB * HH, WW / 32, CC / 32);
        transpose_pad_kernel<<<grid, dim3(32, 32)>>>(x);
    }
    // 3. fused GEMM1+GEMM2 -> g_y, g_xp
    dual_gemm_kernel<<<NPIX / 256, 512, SMEM_DUAL>>>(
        p_bt + 0 * 16384, conv_b, p_bt + 1 * 16384, in_proj_b);
    // 4. depthwise + LN + GELU -> g_d (tf32)
    dw_ln_gelu_kernel<<<NPIX / 8, 256>>>(dw_w, dw_b, ln_g, ln_b);
    // 5. GEMM3 -> g_om (coalesced rows)
    mma_gemm_kernel<<<NPIX / 256, 512, SMEM_DUAL>>>(p_d, p_bt + 2 * 16384, p_bcat, p_om, 0);
    // 6. softmax + bilinear sampling, 8x8 tiles -> g_sam (tf32)
    sample_kernel<<<BB * 64, 512>>>();
    // 7. GEMM4 -> out NCHW (smem transpose staging)
    mma_gemm_kernel<<<NPIX / 256, 512, SMEM_DUAL>>>(p_sam, p_bt + 3 * 16384, out_proj_b, out, 2);
}

// round 8
// speedup vs baseline: 1.4194x; 1.2319x over previous
#include <cuda_runtime.h>
#include <math.h>
#include <stdint.h>

// ---------------- problem constants ----------------
#define BB   8
#define CC   128
#define H0   62
#define W0   62
#define HH   64
#define WW   64
#define HP   66
#define WP   66
#define GG   4
#define PP   9
#define GC   32
#define NPIX (BB*HH*WW)        // 32768
#define OMS  128               // padded om row stride

// ---------------- scratch (device globals) ----------------
__device__ float g_xpad[BB*HH*WW*CC];   // x in NHWC, zero ring
__device__ float g_y   [BB*HH*WW*CC];   // conv1x1 output NHWC
__device__ float g_xp  [BB*HP*WP*CC];   // x_proj padded NHWC
__device__ float g_d   [BB*HH*WW*CC];   // dw+LN+GELU NHWC
__device__ float g_om  [NPIX*OMS];      // offsets(72)+logits(36)+pad
__device__ float g_sam [NPIX*CC];       // sampled NHWC
__device__ float g_bt  [4*128*128];     // 4 pre-transposed tf32 B tiles, [k][n]
__device__ float g_bcat[128];           // padded off/mask bias

// ---------------- helpers ----------------
__device__ __forceinline__ float f2tf(float x) {
    uint32_t u;
    asm("cvt.rn.tf32.f32 %0, %1;" : "=r"(u) : "f"(x));
    return __uint_as_float(u);
}
__device__ __forceinline__ void mma_tf32(float c[4], const uint32_t a[4],
                                         uint32_t b0, uint32_t b1) {
    asm volatile(
        "mma.sync.aligned.m16n8k8.row.col.f32.tf32.tf32.f32 "
        "{%0,%1,%2,%3}, {%4,%5,%6,%7}, {%8,%9}, {%0,%1,%2,%3};"
        : "+f"(c[0]), "+f"(c[1]), "+f"(c[2]), "+f"(c[3])
        : "r"(a[0]), "r"(a[1]), "r"(a[2]), "r"(a[3]), "r"(b0), "r"(b1));
}

// ---------------- weight prep ----------------
__global__ void prep_weights_kernel(const float* __restrict__ conv_w,
                                    const float* __restrict__ in_proj_w,
                                    const float* __restrict__ off_w,
                                    const float* __restrict__ mask_w,
                                    const float* __restrict__ off_b,
                                    const float* __restrict__ mask_b,
                                    const float* __restrict__ out_proj_w) {
    int idx = blockIdx.x * blockDim.x + threadIdx.x;
    const int TB = 4 * 128 * 128;
    if (idx < TB) {
        int w = idx >> 14;
        int rem = idx & 16383;
        int k = rem >> 7, n = rem & 127;
        float v;
        if (w == 0)      v = conv_w[n * 128 + k];
        else if (w == 1) v = in_proj_w[k * 128 + n];
        else if (w == 2) v = (n < 72) ? off_w[k * 72 + n]
                           : (n < 108) ? mask_w[k * 36 + (n - 72)] : 0.f;
        else             v = out_proj_w[k * 128 + n];
        g_bt[idx] = f2tf(v);
    } else if (idx < TB + 128) {
        int n = idx - TB;
        g_bcat[n] = (n < 72) ? off_b[n] : (n < 108) ? mask_b[n - 72] : 0.f;
    }
}

// ---------------- zero only the pad ring of g_xp ----------------
__global__ void ring_zero_kernel() {
    int idx = blockIdx.x * blockDim.x + threadIdx.x;
    if (idx >= BB * 260 * 32) return;
    int c4 = (idx & 31) * 4;
    int t = idx >> 5;
    int b = t / 260, p = t % 260;
    int r, cl;
    if (p < 66)       { r = 0;        cl = p; }
    else if (p < 132) { r = 65;       cl = p - 66; }
    else if (p < 196) { r = p - 131;  cl = 0; }
    else              { r = p - 195;  cl = 65; }
    *reinterpret_cast<float4*>(&g_xp[(((size_t)b * HP + r) * WP + cl) * CC + c4]) =
        make_float4(0.f, 0.f, 0.f, 0.f);
}

// ---------------- NCHW -> NHWC transpose with zero pad ring ----------------
__global__ void transpose_pad_kernel(const float* __restrict__ x) {
    __shared__ float s[32][33];
    int bi = blockIdx.x;
    int b = bi >> 6, i = bi & 63;
    int j0 = blockIdx.y * 32, c0 = blockIdx.z * 32;
    int tx = threadIdx.x, ty = threadIdx.y;
    int j = j0 + tx;
    float v = 0.f;
    if (i >= 1 && i <= 62 && j >= 1 && j <= 62)
        v = x[((b * CC + c0 + ty) * H0 + (i - 1)) * W0 + (j - 1)];
    s[ty][tx] = v;
    __syncthreads();
    int jw = j0 + ty;
    g_xpad[((b * HH + i) * WW + jw) * CC + c0 + tx] = s[tx][ty];
}

// ================= shared GEMM machinery (round-5 proven) =================
#define LDA 132
#define SM_A_ELEMS (256 * LDA)
#define SM_B_ELEMS (128 * LDA)
#define SMEM_GEMM ((SM_A_ELEMS + SM_B_ELEMS) * 4)

struct Frag { float acc[4][4][4]; };

__device__ __forceinline__ void mma_stage(float* sA, float* sB, Frag& F,
                                          int wm, int wn, int g, int tig) {
#pragma unroll
    for (int mt = 0; mt < 4; mt++)
#pragma unroll
        for (int nt = 0; nt < 4; nt++)
#pragma unroll
            for (int q = 0; q < 4; q++) F.acc[mt][nt][q] = 0.f;
#pragma unroll
    for (int ks = 0; ks < 16; ks++) {
        int k0 = ks * 8;
        uint32_t af[4][4];
#pragma unroll
        for (int mt = 0; mt < 4; mt++) {
            int rb = wm * 64 + mt * 16 + g;
            af[mt][0] = __float_as_uint(sA[rb * LDA + k0 + tig]);
            af[mt][1] = __float_as_uint(sA[(rb + 8) * LDA + k0 + tig]);
            af[mt][2] = __float_as_uint(sA[rb * LDA + k0 + tig + 4]);
            af[mt][3] = __float_as_uint(sA[(rb + 8) * LDA + k0 + tig + 4]);
        }
#pragma unroll
        for (int nt = 0; nt < 4; nt++) {
            int cb = wn * 32 + nt * 8 + g;
            uint32_t b0 = __float_as_uint(sB[(k0 + tig) * LDA + cb]);
            uint32_t b1 = __float_as_uint(sB[(k0 + tig + 4) * LDA + cb]);
#pragma unroll
            for (int mt = 0; mt < 4; mt++) mma_tf32(F.acc[mt][nt], af[mt], b0, b1);
        }
    }
}

__device__ __forceinline__ void load_B(const float* __restrict__ Bt, float* sB, int tid) {
#pragma unroll
    for (int it = 0; it < 8; it++) {
        int idx = it * 512 + tid;
        int r = idx >> 5, c4 = (idx & 31) * 4;
        *reinterpret_cast<float4*>(&sB[r * LDA + c4]) =
            *reinterpret_cast<const float4*>(&Bt[(size_t)r * 128 + c4]);
    }
}
__device__ __forceinline__ void load_A(const float* __restrict__ A, float* sA,
                                       int m0, int tid) {
#pragma unroll
    for (int it = 0; it < 16; it++) {
        int idx = it * 512 + tid;
        int r = idx >> 5, c4 = (idx & 31) * 4;
        float4 v = *reinterpret_cast<const float4*>(&A[(size_t)(m0 + r) * 128 + c4]);
        v.x = f2tf(v.x); v.y = f2tf(v.y); v.z = f2tf(v.z); v.w = f2tf(v.w);
        *reinterpret_cast<float4*>(&sA[r * LDA + c4]) = v;
    }
}

// ---------------- fused GEMM1+GEMM2 (round-5 verbatim) ----------------
__global__ __launch_bounds__(512) void dual_gemm_kernel(
    const float* __restrict__ Bt1, const float* __restrict__ bias1,
    const float* __restrict__ Bt2, const float* __restrict__ bias2) {
    extern __shared__ float sm[];
    float* sA = sm;
    float* sB = sm + SM_A_ELEMS;
    int tid = threadIdx.x;
    int w = tid >> 5, lane = tid & 31;
    int g = lane >> 2, tig = lane & 3;
    int wm = w >> 2, wn = w & 3;
    int m0 = blockIdx.x * 256;

    load_A(g_xpad, sA, m0, tid);
    load_B(Bt1, sB, tid);
    __syncthreads();

    Frag F;
    mma_stage(sA, sB, F, wm, wn, g, tig);
    __syncthreads();

#pragma unroll
    for (int mt = 0; mt < 4; mt++) {
        int ml_a = wm * 64 + mt * 16 + g;
        int ml_b = ml_a + 8;
#pragma unroll
        for (int nt = 0; nt < 4; nt++) {
            int cb = wn * 32 + nt * 8 + 2 * tig;
            float bx = __ldg(&bias1[cb]), by = __ldg(&bias1[cb + 1]);
            float ax = F.acc[mt][nt][0] + bx, ay = F.acc[mt][nt][1] + by;
            float bx2 = F.acc[mt][nt][2] + bx, by2 = F.acc[mt][nt][3] + by;
            *reinterpret_cast<float2*>(&g_y[(size_t)(m0 + ml_a) * 128 + cb]) =
                make_float2(ax, ay);
            *reinterpret_cast<float2*>(&g_y[(size_t)(m0 + ml_b) * 128 + cb]) =
                make_float2(bx2, by2);
            sA[ml_a * LDA + cb] = f2tf(ax);
            sA[ml_a * LDA + cb + 1] = f2tf(ay);
            sA[ml_b * LDA + cb] = f2tf(bx2);
            sA[ml_b * LDA + cb + 1] = f2tf(by2);
        }
    }
    load_B(Bt2, sB, tid);
    __syncthreads();

    mma_stage(sA, sB, F, wm, wn, g, tig);

#pragma unroll
    for (int mt = 0; mt < 4; mt++) {
        int m_a = m0 + wm * 64 + mt * 16 + g;
        int m_b = m_a + 8;
        int ba = m_a >> 12, ra = m_a & 4095;
        int bb = m_b >> 12, rb = m_b & 4095;
        int r1 = ra >> 6, c1 = ra & 63;
        int r2 = rb >> 6, c2 = rb & 63;
        float* da = &g_xp[(((size_t)ba * HP + r1 + 1) * WP + c1 + 1) * CC];
        float* db = &g_xp[(((size_t)bb * HP + r2 + 1) * WP + c2 + 1) * CC];
#pragma unroll
        for (int nt = 0; nt < 4; nt++) {
            int cb = wn * 32 + nt * 8 + 2 * tig;
            float bx = __ldg(&bias2[cb]), by = __ldg(&bias2[cb + 1]);
            *reinterpret_cast<float2*>(da + cb) =
                make_float2(F.acc[mt][nt][0] + bx, F.acc[mt][nt][1] + by);
            *reinterpret_cast<float2*>(db + cb) =
                make_float2(F.acc[mt][nt][2] + bx, F.acc[mt][nt][3] + by);
        }
    }
}

// ---------------- single GEMM (round-5 verbatim; modes 0/2) ----------------
__global__ __launch_bounds__(512) void mma_gemm_kernel(
    const float* __restrict__ A, const float* __restrict__ Bt,
    const float* __restrict__ bias, float* __restrict__ C, int mode) {
    extern __shared__ float sm[];
    float* sA = sm;
    float* sB = sm + SM_A_ELEMS;
    int tid = threadIdx.x;
    int w = tid >> 5, lane = tid & 31;
    int g = lane >> 2, tig = lane & 3;
    int wm = w >> 2, wn = w & 3;
    int m0 = blockIdx.x * 256;

    load_A(A, sA, m0, tid);
    load_B(Bt, sB, tid);
    __syncthreads();

    Frag F;
    mma_stage(sA, sB, F, wm, wn, g, tig);

#pragma unroll
    for (int mt = 0; mt < 4; mt++) {
        int m_a = m0 + wm * 64 + mt * 16 + g;
        int m_b = m_a + 8;
        int ba = m_a >> 12, ra = m_a & 4095;
        int bb = m_b >> 12, rb = m_b & 4095;
#pragma unroll
        for (int nt = 0; nt < 4; nt++) {
            int cb = wn * 32 + nt * 8 + 2 * tig;
            float bx = __ldg(&bias[cb]), by = __ldg(&bias[cb + 1]);
            float2 oa = make_float2(F.acc[mt][nt][0] + bx, F.acc[mt][nt][1] + by);
            float2 ob = make_float2(F.acc[mt][nt][2] + bx, F.acc[mt][nt][3] + by);
            if (mode == 0) {
                *reinterpret_cast<float2*>(&C[(size_t)m_a * 128 + cb]) = oa;
                *reinterpret_cast<float2*>(&C[(size_t)m_b * 128 + cb]) = ob;
            } else {
                C[((size_t)ba * CC + cb    ) * 4096 + ra] = oa.x;
                C[((size_t)ba * CC + cb + 1) * 4096 + ra] = oa.y;
                C[((size_t)bb * CC + cb    ) * 4096 + rb] = ob.x;
                C[((size_t)bb * CC + cb + 1) * 4096 + rb] = ob.y;
            }
        }
    }
}

// ---------------- dw3x3 + LN + GELU, horizontal-reuse version ----------------
// CTA = one image row (64 pixels), 256 threads = 8 warps; warp = 8-pixel run.
// Warp loads a 3-row x 10-col window once (30 row-loads vs 72) and scatters
// each column into the <=3 output pixels using it. Weights in registers.
__global__ __launch_bounds__(256) void dw_ln_gelu_kernel(
    const float* __restrict__ dw_w, const float* __restrict__ dw_b,
    const float* __restrict__ ln_g, const float* __restrict__ ln_b) {
    __shared__ float dws[CC * 9];
    int tid = threadIdx.x;
    for (int t = tid; t < CC * 9; t += 256) dws[t] = dw_w[t];
    __syncthreads();

    int warp = tid >> 5, lane = tid & 31;
    int bi = blockIdx.x;
    int b = bi >> 6, i = bi & 63;
    int j0 = warp * 8;
    int c4 = lane * 4;

    float wgt[4][9];
#pragma unroll
    for (int q = 0; q < 4; q++)
#pragma unroll
        for (int t = 0; t < 9; t++) wgt[q][t] = dws[(c4 + q) * 9 + t];

    float4 db = *reinterpret_cast<const float4*>(&dw_b[c4]);
    float v[8][4];
#pragma unroll
    for (int p = 0; p < 8; p++) {
        v[p][0] = db.x; v[p][1] = db.y; v[p][2] = db.z; v[p][3] = db.w;
    }

    bool y0ok = (i >= 1), y2ok = (i <= 62);
    const float* rowm = &g_y[((size_t)(b * HH + i - 1) * WW) * CC + c4];
    const float* row0 = &g_y[((size_t)(b * HH + i    ) * WW) * CC + c4];
    const float* rowp = &g_y[((size_t)(b * HH + i + 1) * WW) * CC + c4];

#pragma unroll
    for (int jj = 0; jj < 10; jj++) {
        int xx = j0 + jj - 1;
        float4 r0 = make_float4(0.f, 0.f, 0.f, 0.f);
        float4 r1 = r0, r2 = r0;
        if ((unsigned)xx < (unsigned)WW) {
            if (y0ok) r0 = *reinterpret_cast<const float4*>(rowm + (size_t)xx * CC);
            r1 = *reinterpret_cast<const float4*>(row0 + (size_t)xx * CC);
            if (y2ok) r2 = *reinterpret_cast<const float4*>(rowp + (size_t)xx * CC);
        }
        float rq[3][4] = {{r0.x, r0.y, r0.z, r0.w},
                          {r1.x, r1.y, r1.z, r1.w},
                          {r2.x, r2.y, r2.z, r2.w}};
#pragma unroll
        for (int p = 0; p < 8; p++) {
            int kx = jj - p;
            if (kx >= 0 && kx <= 2) {
#pragma unroll
                for (int ky = 0; ky < 3; ky++)
#pragma unroll
                    for (int q = 0; q < 4; q++)
                        v[p][q] += rq[ky][q] * wgt[q][ky * 3 + kx];
            }
        }
    }

    float4 lg = *reinterpret_cast<const float4*>(&ln_g[c4]);
    float4 lb = *reinterpret_cast<const float4*>(&ln_b[c4]);
    float gv[4] = {lg.x, lg.y, lg.z, lg.w};
    float bv[4] = {lb.x, lb.y, lb.z, lb.w};

#pragma unroll
    for (int p = 0; p < 8; p++) {
        float s = v[p][0] + v[p][1] + v[p][2] + v[p][3];
#pragma unroll
        for (int o = 16; o; o >>= 1) s += __shfl_xor_sync(0xffffffffu, s, o);
        float mu = s * (1.f / 128.f);
        float d2 = 0.f;
#pragma unroll
        for (int q = 0; q < 4; q++) { float t = v[p][q] - mu; d2 += t * t; }
#pragma unroll
        for (int o = 16; o; o >>= 1) d2 += __shfl_xor_sync(0xffffffffu, d2, o);
        float inv = rsqrtf(d2 * (1.f / 128.f) + 1e-5f);
        float4 outv;
        float* op = reinterpret_cast<float*>(&outv);
#pragma unroll
        for (int q = 0; q < 4; q++) {
            float t = (v[p][q] - mu) * inv * gv[q] + bv[q];
            op[q] = 0.5f * t * (1.f + erff(t * 0.70710678118654752440f));
        }
        int pix = (b << 12) + (i << 6) + j0 + p;
        *reinterpret_cast<float4*>(&g_d[(size_t)pix * CC + c4]) = outv;
    }
}

// ---------------- DCNv3 core: softmax + bilinear sampling (round-5 2x2) ----------------
__global__ __launch_bounds__(512) void sample_kernel() {
    int w = threadIdx.x >> 5, lane = threadIdx.x & 31;
    int pl = w >> 2;
    int g = w & 3;
    int blk = blockIdx.x;
    int tx = blk & 31, ty = (blk >> 5) & 31, b = blk >> 10;
    int i = ty * 2 + (pl >> 1);
    int j = tx * 2 + (pl & 1);
    int pix = (b << 12) + (i << 6) + j;
    const float* omr = g_om + (size_t)pix * OMS;

    float lg[9];
    float mx = -1e30f;
#pragma unroll
    for (int p = 0; p < 9; p++) { lg[p] = omr[72 + g * 9 + p]; mx = fmaxf(mx, lg[p]); }
    float sum = 0.f;
#pragma unroll
    for (int p = 0; p < 9; p++) { lg[p] = expf(lg[p] - mx); sum += lg[p]; }
    float minv = 1.f / sum;

    int cbase = g * GC + lane;
    const float* xpb = g_xp + (size_t)b * (HP * WP * CC);
    float acc = 0.f;
#pragma unroll
    for (int p = 0; p < 9; p++) {
        float offx = omr[(g * 9 + p) * 2 + 0];
        float offy = omr[(g * 9 + p) * 2 + 1];
        float ix = (float)(j + p / 3) + offx;
        float iy = (float)(i + (p - (p / 3) * 3)) + offy;
        float x0f = floorf(ix), y0f = floorf(iy);
        float wx1 = ix - x0f, wy1 = iy - y0f;
        float wx0 = 1.f - wx1, wy0 = 1.f - wy1;
        int x0 = (int)x0f, y0 = (int)y0f;
        float v00 = 0.f, v10 = 0.f, v01 = 0.f, v11 = 0.f;
        bool xv0 = (x0 >= 0) & (x0 < WP);
        bool xv1 = (x0 + 1 >= 0) & (x0 + 1 < WP);
        bool yv0 = (y0 >= 0) & (y0 < HP);
        bool yv1 = (y0 + 1 >= 0) & (y0 + 1 < HP);
        if (yv0) {
            if (xv0) v00 = xpb[(y0 * WP + x0) * CC + cbase];
            if (xv1) v10 = xpb[(y0 * WP + x0 + 1) * CC + cbase];
        }
        if (yv1) {
            if (xv0) v01 = xpb[((y0 + 1) * WP + x0) * CC + cbase];
            if (xv1) v11 = xpb[((y0 + 1) * WP + x0 + 1) * CC + cbase];
        }
        float bi = (v00 * wx0 + v10 * wx1) * wy0 + (v01 * wx0 + v11 * wx1) * wy1;
        acc += (lg[p] * minv) * bi;
    }
    g_sam[(size_t)pix * CC + cbase] = acc;
}

// ---------------- launch ----------------
extern "C" void kernel_launch(void* const* d_in, const int* in_sizes, int n_in,
                              void* d_out, int out_size) {
    const float* x          = (const float*)d_in[0];
    const float* conv_w     = (const float*)d_in[1];
    const float* conv_b     = (const float*)d_in[2];
    const float* in_proj_w  = (const float*)d_in[3];
    const float* in_proj_b  = (const float*)d_in[4];
    const float* dw_w       = (const float*)d_in[5];
    const float* dw_b       = (const float*)d_in[6];
    const float* ln_g       = (const float*)d_in[7];
    const float* ln_b       = (const float*)d_in[8];
    const float* off_w      = (const float*)d_in[9];
    const float* off_b      = (const float*)d_in[10];
    const float* mask_w     = (const float*)d_in[11];
    const float* mask_b     = (const float*)d_in[12];
    const float* out_proj_w = (const float*)d_in[13];
    const float* out_proj_b = (const float*)d_in[14];
    float* out = (float*)d_out;

    float *p_d, *p_om, *p_sam, *p_bt, *p_bcat;
    cudaGetSymbolAddress((void**)&p_d,    g_d);
    cudaGetSymbolAddress((void**)&p_om,   g_om);
    cudaGetSymbolAddress((void**)&p_sam,  g_sam);
    cudaGetSymbolAddress((void**)&p_bt,   g_bt);
    cudaGetSymbolAddress((void**)&p_bcat, g_bcat);

    cudaFuncSetAttribute(dual_gemm_kernel,
                         cudaFuncAttributeMaxDynamicSharedMemorySize, SMEM_GEMM);
    cudaFuncSetAttribute(mma_gemm_kernel,
                         cudaFuncAttributeMaxDynamicSharedMemorySize, SMEM_GEMM);

    // 1. zero pad ring of g_xp
    ring_zero_kernel<<<(BB * 260 * 32 + 255) / 256, 256>>>();
    // 2. weight prep
    prep_weights_kernel<<<(4 * 16384 + 128 + 255) / 256, 256>>>(
        conv_w, in_proj_w, off_w, mask_w, off_b, mask_b, out_proj_w);
    // 3. NCHW -> NHWC transpose + pad
    {
        dim3 grid(BB * HH, WW / 32, CC / 32);
        transpose_pad_kernel<<<grid, dim3(32, 32)>>>(x);
    }
    // 4. fused GEMM1+GEMM2
    dual_gemm_kernel<<<NPIX / 256, 512, SMEM_GEMM>>>(
        p_bt + 0 * 16384, conv_b, p_bt + 1 * 16384, in_proj_b);
    // 5. depthwise + LN + GELU (horizontal-reuse)
    dw_ln_gelu_kernel<<<BB * HH, 256>>>(dw_w, dw_b, ln_g, ln_b);
    // 6. GEMM3: [offset|logits|pad] = d @ wcat + bcat
    mma_gemm_kernel<<<NPIX / 256, 512, SMEM_GEMM>>>(p_d, p_bt + 2 * 16384, p_bcat, p_om, 0);
    // 7. softmax + bilinear sampling (2x2 pixel tiles)
    sample_kernel<<<BB * 32 * 32, 512>>>();
    // 8. GEMM4: out = sampled @ out_proj_w + b, NCHW scatter
    mma_gemm_kernel<<<NPIX / 256, 512, SMEM_GEMM>>>(p_sam, p_bt + 3 * 16384, out_proj_b, out, 2);
}